// round 1
// baseline (speedup 1.0000x reference)
#include <cuda_runtime.h>
#include <math.h>

#define BB 4
#define CC 64
#define C3 192
#define TT 10
#define HH 64
#define WW 64
#define HW 4096
#define THW 40960
#define HEADS 4
#define CPH 16
#define NN 160
#define DD 4096
#define BH (BB*HEADS)

// ---------------- scratch (device globals; no allocations allowed) --------
__device__ float g_qkv0[(size_t)BB * C3 * THW];   // after 1x1 projection
__device__ float g_qkv1[(size_t)BB * C3 * THW];   // after dwconv + temporal mix
__device__ float g_S[(size_t)BH * NN * NN];       // attention scores / probs
__device__ float g_invq[BH * NN];
__device__ float g_invk[BH * NN];
__device__ float g_O[(size_t)BB * CC * THW];      // attention output

// ---------------- K1 / K7: projection GEMM  Y[b][m][p] = sum_k W[m][k] X[b][k][p]
// K = 64 (full), tile 64x64, 256 threads, 4x4 micro-tile per thread.
__global__ __launch_bounds__(256) void gemm_proj(
    const float* __restrict__ W, const float* __restrict__ X, float* __restrict__ Y,
    long xbstride, long ybstride)
{
    __shared__ float As[64][68];  // As[m][k]
    __shared__ float Bs[64][68];  // Bs[p][k]
    const int b  = blockIdx.z;
    const int m0 = blockIdx.y * 64;
    const int p0 = blockIdx.x * 64;
    const float* Xb = X + (size_t)b * xbstride;
    float*       Yb = Y + (size_t)b * ybstride;
    const int tid = threadIdx.x;

    // load W tile (row-major, k contiguous)
    #pragma unroll
    for (int j = 0; j < 4; j++) {
        int row = (tid >> 4) + j * 16;
        int kc  = (tid & 15) * 4;
        float4 v = *(const float4*)&W[(size_t)(m0 + row) * 64 + kc];
        *(float4*)&As[row][kc] = v;
    }
    // load X tile transposed: Bs[p][k] from X[k][p]
    #pragma unroll
    for (int j = 0; j < 4; j++) {
        int c  = (tid >> 4) + j * 16;
        int pc = (tid & 15) * 4;
        float4 v = *(const float4*)&Xb[(size_t)c * THW + p0 + pc];
        Bs[pc + 0][c] = v.x; Bs[pc + 1][c] = v.y;
        Bs[pc + 2][c] = v.z; Bs[pc + 3][c] = v.w;
    }
    __syncthreads();

    const int tm = tid >> 4, tn = tid & 15;
    float acc[4][4] = {};
    #pragma unroll
    for (int k4 = 0; k4 < 64; k4 += 4) {
        float4 a[4], bb[4];
        #pragma unroll
        for (int i = 0; i < 4; i++) a[i]  = *(const float4*)&As[tm * 4 + i][k4];
        #pragma unroll
        for (int i = 0; i < 4; i++) bb[i] = *(const float4*)&Bs[tn * 4 + i][k4];
        #pragma unroll
        for (int mi = 0; mi < 4; mi++)
            #pragma unroll
            for (int ni = 0; ni < 4; ni++) {
                acc[mi][ni] += a[mi].x * bb[ni].x;
                acc[mi][ni] += a[mi].y * bb[ni].y;
                acc[mi][ni] += a[mi].z * bb[ni].z;
                acc[mi][ni] += a[mi].w * bb[ni].w;
            }
    }
    #pragma unroll
    for (int mi = 0; mi < 4; mi++) {
        float4 o = make_float4(acc[mi][0], acc[mi][1], acc[mi][2], acc[mi][3]);
        *(float4*)&Yb[(size_t)(m0 + tm * 4 + mi) * THW + p0 + tn * 4] = o;
    }
}

// ---------------- K2: fused depthwise 3x3 (cross-correlation, zero pad) + temporal mix
__global__ __launch_bounds__(256) void dwconv_tmix(
    const float* __restrict__ wdw, const float* __restrict__ wt,
    const float* __restrict__ bt)
{
    __shared__ float tile[TT][18][18];
    const int bc = blockIdx.z;            // b*192 + c
    const int c  = bc % C3;
    const int h0 = blockIdx.y * 16, w0 = blockIdx.x * 16;
    const float* src = g_qkv0 + (size_t)bc * THW;
    float*       dst = g_qkv1 + (size_t)bc * THW;
    const int tid = threadIdx.x;

    for (int idx = tid; idx < TT * 18 * 18; idx += 256) {
        int t = idx / 324, rem = idx % 324;
        int y = rem / 18, x = rem % 18;
        int gh = h0 + y - 1, gw = w0 + x - 1;
        float v = 0.f;
        if (gh >= 0 && gh < HH && gw >= 0 && gw < WW)
            v = src[(size_t)t * HW + gh * WW + gw];
        tile[t][y][x] = v;
    }
    __syncthreads();

    float wd[9];
    #pragma unroll
    for (int i = 0; i < 9; i++) wd[i] = wdw[c * 9 + i];

    const int y = tid >> 4, x = tid & 15;
    float cv[TT];
    #pragma unroll
    for (int t = 0; t < TT; t++) {
        float s = 0.f;
        #pragma unroll
        for (int kh = 0; kh < 3; kh++)
            #pragma unroll
            for (int kw = 0; kw < 3; kw++)
                s += wd[kh * 3 + kw] * tile[t][y + kh][x + kw];
        cv[t] = s;
    }
    const int hw = (h0 + y) * WW + (w0 + x);
    #pragma unroll
    for (int s = 0; s < TT; s++) {
        float o = bt[s];
        #pragma unroll
        for (int t = 0; t < TT; t++) o += wt[s * TT + t] * cv[t];
        dst[(size_t)s * HW + hw] = o;
    }
}

// ---------------- K3a: L2 norms of q and k rows (one warp per row)
__global__ __launch_bounds__(256) void norms_kernel()
{
    const int warp = (blockIdx.x * 256 + threadIdx.x) >> 5;
    const int lane = threadIdx.x & 31;
    if (warp >= 2 * BH * NN) return;
    const int qk = warp / (BH * NN);
    const int r  = warp % (BH * NN);
    const int bh = r / NN, i = r % NN;
    const int b = bh / HEADS, h = bh % HEADS;
    // contiguous layout: row i of (b,h) sits at base + i*4096
    const float* row = g_qkv1 + ((size_t)b * C3 + qk * CC + h * CPH) * THW + (size_t)i * DD;
    float s = 0.f;
    for (int d = lane * 4; d < DD; d += 128) {
        float4 v = *(const float4*)&row[d];
        s += v.x * v.x + v.y * v.y + v.z * v.z + v.w * v.w;
    }
    #pragma unroll
    for (int off = 16; off; off >>= 1) s += __shfl_xor_sync(0xffffffffu, s, off);
    if (lane == 0) {
        float inv = 1.f / fmaxf(sqrtf(s), 1e-12f);
        (qk ? g_invk : g_invq)[bh * NN + i] = inv;
    }
}

// ---------------- K3b: S = Q K^T (raw dots; scaling folded into softmax)
// per (b,h): 160x160, K=4096. tile 32x32, 2x2 micro, k-chunk 32.
__global__ __launch_bounds__(256) void qk_gemm()
{
    __shared__ float Qs[32][36];
    __shared__ float Ks[32][36];
    const int bh = blockIdx.z;
    const int b = bh / HEADS, h = bh % HEADS;
    const int i0 = blockIdx.y * 32, j0 = blockIdx.x * 32;
    const float* Q  = g_qkv1 + ((size_t)b * C3 + h * CPH) * THW;
    const float* Kp = Q + (size_t)CC * THW;
    const int tid = threadIdx.x;
    const int lrow = tid >> 3, lk = (tid & 7) * 4;
    const int tm = tid >> 4, tn = tid & 15;
    float acc00 = 0.f, acc01 = 0.f, acc10 = 0.f, acc11 = 0.f;

    for (int kb = 0; kb < DD; kb += 32) {
        float4 qa = *(const float4*)&Q [(size_t)(i0 + lrow) * DD + kb + lk];
        float4 ka = *(const float4*)&Kp[(size_t)(j0 + lrow) * DD + kb + lk];
        *(float4*)&Qs[lrow][lk] = qa;
        *(float4*)&Ks[lrow][lk] = ka;
        __syncthreads();
        #pragma unroll
        for (int k4 = 0; k4 < 32; k4 += 4) {
            float4 a0 = *(const float4*)&Qs[tm * 2 + 0][k4];
            float4 a1 = *(const float4*)&Qs[tm * 2 + 1][k4];
            float4 b0 = *(const float4*)&Ks[tn * 2 + 0][k4];
            float4 b1 = *(const float4*)&Ks[tn * 2 + 1][k4];
            acc00 += a0.x*b0.x + a0.y*b0.y + a0.z*b0.z + a0.w*b0.w;
            acc01 += a0.x*b1.x + a0.y*b1.y + a0.z*b1.z + a0.w*b1.w;
            acc10 += a1.x*b0.x + a1.y*b0.y + a1.z*b0.z + a1.w*b0.w;
            acc11 += a1.x*b1.x + a1.y*b1.y + a1.z*b1.z + a1.w*b1.w;
        }
        __syncthreads();
    }
    float* Sb = g_S + (size_t)bh * NN * NN;
    Sb[(size_t)(i0 + tm * 2 + 0) * NN + j0 + tn * 2 + 0] = acc00;
    Sb[(size_t)(i0 + tm * 2 + 0) * NN + j0 + tn * 2 + 1] = acc01;
    Sb[(size_t)(i0 + tm * 2 + 1) * NN + j0 + tn * 2 + 0] = acc10;
    Sb[(size_t)(i0 + tm * 2 + 1) * NN + j0 + tn * 2 + 1] = acc11;
}

// ---------------- K3c: softmax rows (apply inv-norms + temperature here); in place
__global__ __launch_bounds__(256) void softmax_kernel(const float* __restrict__ temp)
{
    const int warp = (blockIdx.x * 256 + threadIdx.x) >> 5;
    const int lane = threadIdx.x & 31;
    if (warp >= BH * NN) return;
    const int bh = warp / NN, i = warp % NN;
    const int h = bh % HEADS;
    float* row = g_S + (size_t)bh * NN * NN + (size_t)i * NN;
    const float scale_i = g_invq[bh * NN + i] * temp[h];
    float vals[5];
    float mx = -1e30f;
    #pragma unroll
    for (int j5 = 0; j5 < 5; j5++) {
        int j = lane + j5 * 32;
        vals[j5] = row[j] * scale_i * g_invk[bh * NN + j];
        mx = fmaxf(mx, vals[j5]);
    }
    #pragma unroll
    for (int off = 16; off; off >>= 1) mx = fmaxf(mx, __shfl_xor_sync(0xffffffffu, mx, off));
    float s = 0.f;
    #pragma unroll
    for (int j5 = 0; j5 < 5; j5++) { vals[j5] = __expf(vals[j5] - mx); s += vals[j5]; }
    #pragma unroll
    for (int off = 16; off; off >>= 1) s += __shfl_xor_sync(0xffffffffu, s, off);
    const float invs = 1.f / s;
    #pragma unroll
    for (int j5 = 0; j5 < 5; j5++) row[lane + j5 * 32] = vals[j5] * invs;
}

// ---------------- K3d: O = P V   per (b,h): (160x160)x(160x4096)
// tile 32(i) x 128(d), k-chunk 32, 2x8 micro.
__global__ __launch_bounds__(256) void pv_gemm()
{
    __shared__ float Ps[32][36];    // Ps[i][k]
    __shared__ float Vs[32][132];   // Vs[k][d]
    const int bh = blockIdx.z;
    const int b = bh / HEADS, h = bh % HEADS;
    const int i0 = blockIdx.y * 32;
    const int d0 = blockIdx.x * 128;
    const float* P = g_S + (size_t)bh * NN * NN;
    const float* V = g_qkv1 + ((size_t)b * C3 + 2 * CC + h * CPH) * THW;
    float*       O = g_O   + ((size_t)b * CC + h * CPH) * THW;
    const int tid = threadIdx.x;
    const int tm = tid >> 4, tn = tid & 15;
    float acc[2][8] = {};

    for (int kb = 0; kb < NN; kb += 32) {
        {   // load P tile 32x32
            int lr = tid >> 3, lk = (tid & 7) * 4;
            float4 v = *(const float4*)&P[(size_t)(i0 + lr) * NN + kb + lk];
            *(float4*)&Ps[lr][lk] = v;
        }
        {   // load V tile 32x128
            int vd = (tid & 31) * 4;
            #pragma unroll
            for (int jj = 0; jj < 4; jj++) {
                int vk = (tid >> 5) + jj * 8;
                float4 v = *(const float4*)&V[(size_t)(kb + vk) * DD + d0 + vd];
                *(float4*)&Vs[vk][vd] = v;
            }
        }
        __syncthreads();
        #pragma unroll
        for (int k = 0; k < 32; k++) {
            float a0 = Ps[tm * 2 + 0][k];
            float a1 = Ps[tm * 2 + 1][k];
            float4 blo = *(const float4*)&Vs[k][tn * 8];
            float4 bhi = *(const float4*)&Vs[k][tn * 8 + 4];
            acc[0][0] += a0 * blo.x; acc[0][1] += a0 * blo.y;
            acc[0][2] += a0 * blo.z; acc[0][3] += a0 * blo.w;
            acc[0][4] += a0 * bhi.x; acc[0][5] += a0 * bhi.y;
            acc[0][6] += a0 * bhi.z; acc[0][7] += a0 * bhi.w;
            acc[1][0] += a1 * blo.x; acc[1][1] += a1 * blo.y;
            acc[1][2] += a1 * blo.z; acc[1][3] += a1 * blo.w;
            acc[1][4] += a1 * bhi.x; acc[1][5] += a1 * bhi.y;
            acc[1][6] += a1 * bhi.z; acc[1][7] += a1 * bhi.w;
        }
        __syncthreads();
    }
    #pragma unroll
    for (int mi = 0; mi < 2; mi++) {
        size_t base = (size_t)(i0 + tm * 2 + mi) * DD + d0 + tn * 8;
        *(float4*)&O[base]     = make_float4(acc[mi][0], acc[mi][1], acc[mi][2], acc[mi][3]);
        *(float4*)&O[base + 4] = make_float4(acc[mi][4], acc[mi][5], acc[mi][6], acc[mi][7]);
    }
}

// ---------------- host launcher --------------------------------------------
extern "C" void kernel_launch(void* const* d_in, const int* in_sizes, int n_in,
                              void* d_out, int out_size)
{
    const float* x      = (const float*)d_in[0];
    const float* w_qkv  = (const float*)d_in[1];
    const float* w_dw   = (const float*)d_in[2];
    const float* w_t    = (const float*)d_in[3];
    const float* b_t    = (const float*)d_in[4];
    const float* temp   = (const float*)d_in[5];
    const float* w_out  = (const float*)d_in[6];
    float* out = (float*)d_out;

    float *qkv0, *obuf;
    cudaGetSymbolAddress((void**)&qkv0, g_qkv0);
    cudaGetSymbolAddress((void**)&obuf, g_O);

    // K1: qkv = x * w_qkv^T   (192 x 40960 per batch)
    gemm_proj<<<dim3(THW / 64, C3 / 64, BB), 256>>>(
        w_qkv, x, qkv0, (long)CC * THW, (long)C3 * THW);

    // K2: depthwise 3x3 + temporal mix (fused)
    dwconv_tmix<<<dim3(4, 4, BB * C3), 256>>>(w_dw, w_t, b_t);

    // K3a: q/k row norms
    norms_kernel<<<640, 256>>>();

    // K3b: raw scores
    qk_gemm<<<dim3(5, 5, BH), 256>>>();

    // K3c: scale + softmax
    softmax_kernel<<<(BH * NN) / 8, 256>>>(temp);

    // K3d: O = P V
    pv_gemm<<<dim3(DD / 128, 5, BH), 256>>>();

    // K7: final projection -> d_out
    gemm_proj<<<dim3(THW / 64, 1, BB), 256>>>(
        w_out, obuf, out, (long)CC * THW, (long)CC * THW);
}

// round 2
// speedup vs baseline: 1.8468x; 1.8468x over previous
#include <cuda_runtime.h>
#include <math.h>

#define BB 4
#define CC 64
#define C3 192
#define TT 10
#define HH 64
#define WW 64
#define HW 4096
#define THW 40960
#define HEADS 4
#define CPH 16
#define NN 160
#define DD 4096
#define BH (BB*HEADS)
#define KSPL 16
#define KCH (DD/KSPL)   // 256

// ---------------- scratch (device globals) ---------------------------------
__device__ float g_qkv0[(size_t)BB * C3 * THW];
__device__ float g_qkv1[(size_t)BB * C3 * THW];
__device__ float g_Spart[(size_t)KSPL * BH * NN * NN];  // split-K partials
__device__ float g_S[(size_t)BH * NN * NN];             // softmax probs
__device__ float g_invq[BH * NN];
__device__ float g_invk[BH * NN];
__device__ float g_O[(size_t)BB * CC * THW];

// ---------------- K1 / K7: projection GEMM ---------------------------------
// Y[b][m][p] = sum_k W[m][k] X[b][k][p];  tile 64(m) x 128(p), micro 8x8,
// 128 threads, K chunked by 32.
__global__ __launch_bounds__(128) void gemm_proj2(
    const float* __restrict__ W, const float* __restrict__ X, float* __restrict__ Y,
    long xbstride, long ybstride)
{
    __shared__ float As[32][68];   // [k][m]
    __shared__ float Bs[32][132];  // [k][p]
    const int b  = blockIdx.z;
    const int m0 = blockIdx.y * 64;
    const int p0 = blockIdx.x * 128;
    const float* Xb = X + (size_t)b * xbstride;
    float*       Yb = Y + (size_t)b * ybstride;
    const int tid = threadIdx.x;
    const int tm = tid >> 4, tn = tid & 15;

    float acc[8][8] = {};
    for (int kb = 0; kb < 64; kb += 32) {
        // W tile 64m x 32k, transposed into As[k][m]
        #pragma unroll
        for (int j = 0; j < 4; j++) {
            int idx = tid + j * 128;           // 0..511
            int row = idx >> 3;                // m 0..63
            int kc  = (idx & 7) * 4;
            float4 w4 = *(const float4*)&W[(size_t)(m0 + row) * 64 + kb + kc];
            As[kc + 0][row] = w4.x; As[kc + 1][row] = w4.y;
            As[kc + 2][row] = w4.z; As[kc + 3][row] = w4.w;
        }
        // X tile 32k x 128p
        #pragma unroll
        for (int j = 0; j < 8; j++) {
            int idx = tid + j * 128;           // 0..1023
            int row = idx >> 5;                // k 0..31
            int col = (idx & 31) * 4;
            float4 v = *(const float4*)&Xb[(size_t)(kb + row) * THW + p0 + col];
            *(float4*)&Bs[row][col] = v;
        }
        __syncthreads();
        #pragma unroll 4
        for (int k = 0; k < 32; k++) {
            float a[8], bb[8];
            float4 a0 = *(const float4*)&As[k][tm * 8];
            float4 a1 = *(const float4*)&As[k][tm * 8 + 4];
            float4 b0 = *(const float4*)&Bs[k][tn * 8];
            float4 b1 = *(const float4*)&Bs[k][tn * 8 + 4];
            a[0]=a0.x;a[1]=a0.y;a[2]=a0.z;a[3]=a0.w;a[4]=a1.x;a[5]=a1.y;a[6]=a1.z;a[7]=a1.w;
            bb[0]=b0.x;bb[1]=b0.y;bb[2]=b0.z;bb[3]=b0.w;bb[4]=b1.x;bb[5]=b1.y;bb[6]=b1.z;bb[7]=b1.w;
            #pragma unroll
            for (int mi = 0; mi < 8; mi++)
                #pragma unroll
                for (int ni = 0; ni < 8; ni++)
                    acc[mi][ni] += a[mi] * bb[ni];
        }
        __syncthreads();
    }
    #pragma unroll
    for (int mi = 0; mi < 8; mi++) {
        size_t base = (size_t)(m0 + tm * 8 + mi) * THW + p0 + tn * 8;
        *(float4*)&Yb[base]     = make_float4(acc[mi][0], acc[mi][1], acc[mi][2], acc[mi][3]);
        *(float4*)&Yb[base + 4] = make_float4(acc[mi][4], acc[mi][5], acc[mi][6], acc[mi][7]);
    }
}

// ---------------- K2: depthwise 3x3 + temporal mix (fused) ------------------
__global__ __launch_bounds__(256) void dwconv_tmix(
    const float* __restrict__ wdw, const float* __restrict__ wt,
    const float* __restrict__ bt)
{
    __shared__ float tile[TT][18][18];
    const int bc = blockIdx.z;
    const int c  = bc % C3;
    const int h0 = blockIdx.y * 16, w0 = blockIdx.x * 16;
    const float* src = g_qkv0 + (size_t)bc * THW;
    float*       dst = g_qkv1 + (size_t)bc * THW;
    const int tid = threadIdx.x;

    for (int idx = tid; idx < TT * 18 * 18; idx += 256) {
        int t = idx / 324, rem = idx % 324;
        int y = rem / 18, x = rem % 18;
        int gh = h0 + y - 1, gw = w0 + x - 1;
        float v = 0.f;
        if (gh >= 0 && gh < HH && gw >= 0 && gw < WW)
            v = src[(size_t)t * HW + gh * WW + gw];
        tile[t][y][x] = v;
    }
    __syncthreads();

    float wd[9];
    #pragma unroll
    for (int i = 0; i < 9; i++) wd[i] = wdw[c * 9 + i];

    const int y = tid >> 4, x = tid & 15;
    float cv[TT];
    #pragma unroll
    for (int t = 0; t < TT; t++) {
        float s = 0.f;
        #pragma unroll
        for (int kh = 0; kh < 3; kh++)
            #pragma unroll
            for (int kw = 0; kw < 3; kw++)
                s += wd[kh * 3 + kw] * tile[t][y + kh][x + kw];
        cv[t] = s;
    }
    const int hw = (h0 + y) * WW + (w0 + x);
    #pragma unroll
    for (int s = 0; s < TT; s++) {
        float o = bt[s];
        #pragma unroll
        for (int t = 0; t < TT; t++) o += wt[s * TT + t] * cv[t];
        dst[(size_t)s * HW + hw] = o;
    }
}

// ---------------- K3a: L2 norms of q/k rows ---------------------------------
__global__ __launch_bounds__(256) void norms_kernel()
{
    const int warp = (blockIdx.x * 256 + threadIdx.x) >> 5;
    const int lane = threadIdx.x & 31;
    if (warp >= 2 * BH * NN) return;
    const int qk = warp / (BH * NN);
    const int r  = warp % (BH * NN);
    const int bh = r / NN, i = r % NN;
    const int b = bh / HEADS, h = bh % HEADS;
    const float* row = g_qkv1 + ((size_t)b * C3 + qk * CC + h * CPH) * THW + (size_t)i * DD;
    float s = 0.f;
    for (int d = lane * 4; d < DD; d += 128) {
        float4 v = *(const float4*)&row[d];
        s += v.x * v.x + v.y * v.y + v.z * v.z + v.w * v.w;
    }
    #pragma unroll
    for (int off = 16; off; off >>= 1) s += __shfl_xor_sync(0xffffffffu, s, off);
    if (lane == 0) {
        float inv = 1.f / fmaxf(sqrtf(s), 1e-12f);
        (qk ? g_invk : g_invq)[bh * NN + i] = inv;
    }
}

// ---------------- K3b: S partials = Q K^T, split-K --------------------------
// One block per (bh, ksplit): full 160x160 tile, micro 10x10, 256 threads.
__global__ __launch_bounds__(256) void qk_gemm2()
{
    __shared__ float Qs[32][162];   // [k][i]
    __shared__ float Ks[32][162];   // [k][j]
    const int bh = blockIdx.x;
    const int ks = blockIdx.y;
    const int b = bh >> 2, h = bh & 3;
    const float* Q  = g_qkv1 + ((size_t)b * C3 + h * CPH) * THW;
    const float* Kp = Q + (size_t)CC * THW;
    const int tid = threadIdx.x;
    const int tm = tid >> 4, tn = tid & 15;

    float acc[10][10] = {};
    for (int c = 0; c < 8; c++) {
        const int kb = ks * KCH + c * 32;
        #pragma unroll
        for (int j = 0; j < 5; j++) {
            int idx = tid + j * 256;      // 0..1279
            int row = idx >> 3;           // 0..159
            int kc  = (idx & 7) * 4;
            float4 q4 = *(const float4*)&Q [(size_t)row * DD + kb + kc];
            float4 k4 = *(const float4*)&Kp[(size_t)row * DD + kb + kc];
            Qs[kc + 0][row] = q4.x; Qs[kc + 1][row] = q4.y;
            Qs[kc + 2][row] = q4.z; Qs[kc + 3][row] = q4.w;
            Ks[kc + 0][row] = k4.x; Ks[kc + 1][row] = k4.y;
            Ks[kc + 2][row] = k4.z; Ks[kc + 3][row] = k4.w;
        }
        __syncthreads();
        #pragma unroll 4
        for (int k = 0; k < 32; k++) {
            float a[10], bb[10];
            #pragma unroll
            for (int u = 0; u < 5; u++) {
                float2 va = *(const float2*)&Qs[k][tm * 10 + u * 2];
                a[u * 2] = va.x; a[u * 2 + 1] = va.y;
                float2 vb = *(const float2*)&Ks[k][tn * 10 + u * 2];
                bb[u * 2] = vb.x; bb[u * 2 + 1] = vb.y;
            }
            #pragma unroll
            for (int i = 0; i < 10; i++)
                #pragma unroll
                for (int j2 = 0; j2 < 10; j2++)
                    acc[i][j2] += a[i] * bb[j2];
        }
        __syncthreads();
    }
    float* Sp = g_Spart + ((size_t)ks * BH + bh) * NN * NN;
    #pragma unroll
    for (int i = 0; i < 10; i++) {
        int gi = tm * 10 + i;
        #pragma unroll
        for (int u = 0; u < 5; u++)
            *(float2*)&Sp[(size_t)gi * NN + tn * 10 + u * 2] =
                make_float2(acc[i][u * 2], acc[i][u * 2 + 1]);
    }
}

// ---------------- K3c: reduce split-K partials + scale + softmax ------------
__global__ __launch_bounds__(256) void softmax2(const float* __restrict__ temp)
{
    const int warp = (blockIdx.x * 256 + threadIdx.x) >> 5;
    const int lane = threadIdx.x & 31;
    if (warp >= BH * NN) return;
    const int bh = warp / NN, i = warp % NN;
    const int h = bh & 3;
    const float scale_i = g_invq[bh * NN + i] * temp[h];
    float vals[5];
    float mx = -1e30f;
    #pragma unroll
    for (int j5 = 0; j5 < 5; j5++) {
        int j = lane + j5 * 32;
        float s = 0.f;
        #pragma unroll
        for (int ks = 0; ks < KSPL; ks++)
            s += g_Spart[(((size_t)ks * BH + bh) * NN + i) * NN + j];
        vals[j5] = s * scale_i * g_invk[bh * NN + j];
        mx = fmaxf(mx, vals[j5]);
    }
    #pragma unroll
    for (int off = 16; off; off >>= 1) mx = fmaxf(mx, __shfl_xor_sync(0xffffffffu, mx, off));
    float s = 0.f;
    #pragma unroll
    for (int j5 = 0; j5 < 5; j5++) { vals[j5] = __expf(vals[j5] - mx); s += vals[j5]; }
    #pragma unroll
    for (int off = 16; off; off >>= 1) s += __shfl_xor_sync(0xffffffffu, s, off);
    const float invs = 1.f / s;
    float* row = g_S + (size_t)bh * NN * NN + (size_t)i * NN;
    #pragma unroll
    for (int j5 = 0; j5 < 5; j5++) row[lane + j5 * 32] = vals[j5] * invs;
}

// ---------------- K3d: O = P V ----------------------------------------------
// tile 80(i) x 128(d), micro 5x8, 256 threads, k chunked by 32.
__global__ __launch_bounds__(256) void pv_gemm2()
{
    __shared__ float Ps[80][36];    // [i][k]
    __shared__ float Vs[32][132];   // [k][d]
    const int bh = blockIdx.z;
    const int b = bh >> 2, h = bh & 3;
    const int i0 = blockIdx.y * 80;
    const int d0 = blockIdx.x * 128;
    const float* P = g_S + (size_t)bh * NN * NN;
    const float* V = g_qkv1 + ((size_t)b * C3 + 2 * CC + h * CPH) * THW;
    float*       O = g_O   + ((size_t)b * CC + h * CPH) * THW;
    const int tid = threadIdx.x;
    const int tm = tid >> 4, tn = tid & 15;

    float acc[5][8] = {};
    for (int kb = 0; kb < NN; kb += 32) {
        // P tile 80 x 32 -> Ps[i][k]
        #pragma unroll
        for (int j = 0; j < 3; j++) {
            int idx = tid + j * 256;         // need 0..639
            if (idx < 640) {
                int row = idx >> 3;          // 0..79
                int col = (idx & 7) * 4;
                float4 v = *(const float4*)&P[(size_t)(i0 + row) * NN + kb + col];
                *(float4*)&Ps[row][col] = v;
            }
        }
        // V tile 32 x 128 -> Vs[k][d]
        #pragma unroll
        for (int j = 0; j < 4; j++) {
            int idx = tid + j * 256;         // 0..1023
            int row = idx >> 5;              // 0..31
            int col = (idx & 31) * 4;
            float4 v = *(const float4*)&V[(size_t)(kb + row) * DD + d0 + col];
            *(float4*)&Vs[row][col] = v;
        }
        __syncthreads();
        #pragma unroll 4
        for (int k = 0; k < 32; k++) {
            float a[5];
            #pragma unroll
            for (int v = 0; v < 5; v++) a[v] = Ps[tm * 5 + v][k];
            float4 b0 = *(const float4*)&Vs[k][tn * 8];
            float4 b1 = *(const float4*)&Vs[k][tn * 8 + 4];
            float bb[8] = {b0.x, b0.y, b0.z, b0.w, b1.x, b1.y, b1.z, b1.w};
            #pragma unroll
            for (int v = 0; v < 5; v++)
                #pragma unroll
                for (int ni = 0; ni < 8; ni++)
                    acc[v][ni] += a[v] * bb[ni];
        }
        __syncthreads();
    }
    #pragma unroll
    for (int v = 0; v < 5; v++) {
        size_t base = (size_t)(i0 + tm * 5 + v) * DD + d0 + tn * 8;
        *(float4*)&O[base]     = make_float4(acc[v][0], acc[v][1], acc[v][2], acc[v][3]);
        *(float4*)&O[base + 4] = make_float4(acc[v][4], acc[v][5], acc[v][6], acc[v][7]);
    }
}

// ---------------- host launcher --------------------------------------------
extern "C" void kernel_launch(void* const* d_in, const int* in_sizes, int n_in,
                              void* d_out, int out_size)
{
    const float* x      = (const float*)d_in[0];
    const float* w_qkv  = (const float*)d_in[1];
    const float* w_dw   = (const float*)d_in[2];
    const float* w_t    = (const float*)d_in[3];
    const float* b_t    = (const float*)d_in[4];
    const float* temp   = (const float*)d_in[5];
    const float* w_out  = (const float*)d_in[6];
    float* out = (float*)d_out;

    float *qkv0, *obuf;
    cudaGetSymbolAddress((void**)&qkv0, g_qkv0);
    cudaGetSymbolAddress((void**)&obuf, g_O);

    // K1: qkv = w_qkv * x   (192 x 40960 per batch)
    gemm_proj2<<<dim3(THW / 128, C3 / 64, BB), 128>>>(
        w_qkv, x, qkv0, (long)CC * THW, (long)C3 * THW);

    // K2: depthwise 3x3 + temporal mix
    dwconv_tmix<<<dim3(4, 4, BB * C3), 256>>>(w_dw, w_t, b_t);

    // K3a: q/k row norms
    norms_kernel<<<640, 256>>>();

    // K3b: split-K scores
    qk_gemm2<<<dim3(BH, KSPL), 256>>>();

    // K3c: reduce + scale + softmax
    softmax2<<<(BH * NN) / 8, 256>>>(temp);

    // K3d: O = P V
    pv_gemm2<<<dim3(DD / 128, NN / 80, BH), 256>>>();

    // K7: final projection -> d_out
    gemm_proj2<<<dim3(THW / 128, 1, BB), 128>>>(
        w_out, obuf, out, (long)CC * THW, (long)CC * THW);
}

// round 3
// speedup vs baseline: 1.8885x; 1.0226x over previous
#include <cuda_runtime.h>
#include <math.h>

#define BB 4
#define CC 64
#define C3 192
#define TT 10
#define HH 64
#define WW 64
#define HW 4096
#define THW 40960
#define HEADS 4
#define CPH 16
#define NN 160
#define DD 4096
#define BH (BB*HEADS)
#define KSPL 16
#define KCH (DD/KSPL)   // 256

// ---------------- scratch (device globals) ---------------------------------
__device__ float g_qkv0[(size_t)BB * C3 * THW];
__device__ float g_qkv1[(size_t)BB * C3 * THW];
__device__ float g_Spart[(size_t)KSPL * BH * NN * NN];
__device__ float g_S[(size_t)BH * NN * NN];
__device__ float g_invq[BH * NN];
__device__ float g_invk[BH * NN];
__device__ float g_O[(size_t)BB * CC * THW];

// ---------------- packed f32x2 helpers --------------------------------------
__device__ __forceinline__ void ffma2(unsigned long long& d,
                                      unsigned long long a, unsigned long long b) {
    asm("fma.rn.f32x2 %0, %1, %2, %0;" : "+l"(d) : "l"(a), "l"(b));
}
__device__ __forceinline__ unsigned long long dup2(float x) {
    unsigned long long r;
    asm("mov.b64 %0, {%1, %1};" : "=l"(r) : "f"(x));
    return r;
}
__device__ __forceinline__ float2 unpk(unsigned long long v) {
    float2 r;
    asm("mov.b64 {%0, %1}, %2;" : "=f"(r.x), "=f"(r.y) : "l"(v));
    return r;
}
__device__ __forceinline__ unsigned long long lds64(const float* p) {
    return *(const unsigned long long*)p;
}

// ---------------- K1 / K7: projection GEMM ---------------------------------
// Y[b][m][p] = sum_k W[m][k] X[b][k][p]; tile 64(m) x 128(p), micro 8x(4x2),
// 128 threads, FFMA2 inner.
__global__ __launch_bounds__(128) void gemm_proj2(
    const float* __restrict__ W, const float* __restrict__ X, float* __restrict__ Y,
    long xbstride, long ybstride)
{
    __shared__ __align__(16) float As2[32][132];  // [k][2*m] duplicated
    __shared__ __align__(16) float Bs[32][132];   // [k][p]
    const int b  = blockIdx.z;
    const int m0 = blockIdx.y * 64;
    const int p0 = blockIdx.x * 128;
    const float* Xb = X + (size_t)b * xbstride;
    float*       Yb = Y + (size_t)b * ybstride;
    const int tid = threadIdx.x;
    const int tm = tid >> 4, tn = tid & 15;

    unsigned long long acc[8][4];
    #pragma unroll
    for (int i = 0; i < 8; i++)
        #pragma unroll
        for (int j = 0; j < 4; j++) acc[i][j] = 0ull;

    for (int kb = 0; kb < 64; kb += 32) {
        // W tile 64m x 32k -> As2[k][2m] duplicated
        #pragma unroll
        for (int j = 0; j < 4; j++) {
            int idx = tid + j * 128;        // 0..511
            int row = idx >> 3;             // m 0..63
            int kc  = (idx & 7) * 4;
            float4 w4 = *(const float4*)&W[(size_t)(m0 + row) * 64 + kb + kc];
            *(unsigned long long*)&As2[kc + 0][2 * row] = dup2(w4.x);
            *(unsigned long long*)&As2[kc + 1][2 * row] = dup2(w4.y);
            *(unsigned long long*)&As2[kc + 2][2 * row] = dup2(w4.z);
            *(unsigned long long*)&As2[kc + 3][2 * row] = dup2(w4.w);
        }
        // X tile 32k x 128p
        #pragma unroll
        for (int j = 0; j < 8; j++) {
            int idx = tid + j * 128;
            int row = idx >> 5;
            int col = (idx & 31) * 4;
            *(float4*)&Bs[row][col] = *(const float4*)&Xb[(size_t)(kb + row) * THW + p0 + col];
        }
        __syncthreads();
        #pragma unroll 4
        for (int k = 0; k < 32; k++) {
            unsigned long long a[8], bp[4];
            #pragma unroll
            for (int mi = 0; mi < 8; mi++) a[mi] = lds64(&As2[k][2 * (tm * 8 + mi)]);
            #pragma unroll
            for (int u = 0; u < 4; u++)    bp[u] = lds64(&Bs[k][2 * tn + 32 * u]);
            #pragma unroll
            for (int mi = 0; mi < 8; mi++)
                #pragma unroll
                for (int u = 0; u < 4; u++) ffma2(acc[mi][u], a[mi], bp[u]);
        }
        __syncthreads();
    }
    #pragma unroll
    for (int mi = 0; mi < 8; mi++) {
        size_t base = (size_t)(m0 + tm * 8 + mi) * THW + p0 + 2 * tn;
        #pragma unroll
        for (int u = 0; u < 4; u++)
            *(float2*)&Yb[base + 32 * u] = unpk(acc[mi][u]);
    }
}

// ---------------- K2: depthwise 3x3 + temporal mix (fused) ------------------
__global__ __launch_bounds__(256) void dwconv_tmix(
    const float* __restrict__ wdw, const float* __restrict__ wt,
    const float* __restrict__ bt)
{
    __shared__ float tile[TT][18][18];
    const int bc = blockIdx.z;
    const int c  = bc % C3;
    const int h0 = blockIdx.y * 16, w0 = blockIdx.x * 16;
    const float* src = g_qkv0 + (size_t)bc * THW;
    float*       dst = g_qkv1 + (size_t)bc * THW;
    const int tid = threadIdx.x;

    for (int idx = tid; idx < TT * 18 * 18; idx += 256) {
        int t = idx / 324, rem = idx % 324;
        int y = rem / 18, x = rem % 18;
        int gh = h0 + y - 1, gw = w0 + x - 1;
        float v = 0.f;
        if (gh >= 0 && gh < HH && gw >= 0 && gw < WW)
            v = src[(size_t)t * HW + gh * WW + gw];
        tile[t][y][x] = v;
    }
    __syncthreads();

    float wd[9];
    #pragma unroll
    for (int i = 0; i < 9; i++) wd[i] = wdw[c * 9 + i];

    const int y = tid >> 4, x = tid & 15;
    float cv[TT];
    #pragma unroll
    for (int t = 0; t < TT; t++) {
        float s = 0.f;
        #pragma unroll
        for (int kh = 0; kh < 3; kh++)
            #pragma unroll
            for (int kw = 0; kw < 3; kw++)
                s += wd[kh * 3 + kw] * tile[t][y + kh][x + kw];
        cv[t] = s;
    }
    const int hw = (h0 + y) * WW + (w0 + x);
    #pragma unroll
    for (int s = 0; s < TT; s++) {
        float o = bt[s];
        #pragma unroll
        for (int t = 0; t < TT; t++) o += wt[s * TT + t] * cv[t];
        dst[(size_t)s * HW + hw] = o;
    }
}

// ---------------- K3a: L2 norms of q/k rows ---------------------------------
__global__ __launch_bounds__(256) void norms_kernel()
{
    const int warp = (blockIdx.x * 256 + threadIdx.x) >> 5;
    const int lane = threadIdx.x & 31;
    if (warp >= 2 * BH * NN) return;
    const int qk = warp / (BH * NN);
    const int r  = warp % (BH * NN);
    const int bh = r / NN, i = r % NN;
    const int b = bh / HEADS, h = bh % HEADS;
    const float* row = g_qkv1 + ((size_t)b * C3 + qk * CC + h * CPH) * THW + (size_t)i * DD;
    float s = 0.f;
    for (int d = lane * 4; d < DD; d += 128) {
        float4 v = *(const float4*)&row[d];
        s += v.x * v.x + v.y * v.y + v.z * v.z + v.w * v.w;
    }
    #pragma unroll
    for (int off = 16; off; off >>= 1) s += __shfl_xor_sync(0xffffffffu, s, off);
    if (lane == 0) {
        float inv = 1.f / fmaxf(sqrtf(s), 1e-12f);
        (qk ? g_invk : g_invq)[bh * NN + i] = inv;
    }
}

// ---------------- K3b: S partials = Q K^T, split-K, FFMA2 -------------------
// One block per (bh, ksplit): 160x160 tile, micro 10x(5x2), 256 threads.
// Dynamic smem: Qs2[32][324] duplicated, Ks[32][164].
__global__ __launch_bounds__(256) void qk_gemm3()
{
    extern __shared__ __align__(16) float sm[];
    float (*Qs2)[324] = (float(*)[324])sm;                    // [k][2*i]
    float (*Ks)[164]  = (float(*)[164])(sm + 32 * 324);       // [k][j]
    const int bh = blockIdx.x;
    const int ks = blockIdx.y;
    const int b = bh >> 2, h = bh & 3;
    const float* Q  = g_qkv1 + ((size_t)b * C3 + h * CPH) * THW;
    const float* Kp = Q + (size_t)CC * THW;
    const int tid = threadIdx.x;
    const int tm = tid >> 4, tn = tid & 15;

    unsigned long long acc[10][5];
    #pragma unroll
    for (int i = 0; i < 10; i++)
        #pragma unroll
        for (int j = 0; j < 5; j++) acc[i][j] = 0ull;

    for (int c = 0; c < 8; c++) {
        const int kb = ks * KCH + c * 32;
        #pragma unroll
        for (int j = 0; j < 5; j++) {
            int idx = tid + j * 256;     // 0..1279
            int row = idx >> 3;          // 0..159
            int kc  = (idx & 7) * 4;
            float4 q4 = *(const float4*)&Q [(size_t)row * DD + kb + kc];
            float4 k4 = *(const float4*)&Kp[(size_t)row * DD + kb + kc];
            *(unsigned long long*)&Qs2[kc + 0][2 * row] = dup2(q4.x);
            *(unsigned long long*)&Qs2[kc + 1][2 * row] = dup2(q4.y);
            *(unsigned long long*)&Qs2[kc + 2][2 * row] = dup2(q4.z);
            *(unsigned long long*)&Qs2[kc + 3][2 * row] = dup2(q4.w);
            Ks[kc + 0][row] = k4.x; Ks[kc + 1][row] = k4.y;
            Ks[kc + 2][row] = k4.z; Ks[kc + 3][row] = k4.w;
        }
        __syncthreads();
        #pragma unroll 4
        for (int k = 0; k < 32; k++) {
            unsigned long long a[10], bp[5];
            #pragma unroll
            for (int i = 0; i < 10; i++) a[i] = lds64(&Qs2[k][20 * tm + 2 * i]);
            #pragma unroll
            for (int u = 0; u < 5; u++) bp[u] = lds64(&Ks[k][10 * tn + 2 * u]);
            #pragma unroll
            for (int i = 0; i < 10; i++)
                #pragma unroll
                for (int u = 0; u < 5; u++) ffma2(acc[i][u], a[i], bp[u]);
        }
        __syncthreads();
    }
    float* Sp = g_Spart + ((size_t)ks * BH + bh) * NN * NN;
    #pragma unroll
    for (int i = 0; i < 10; i++) {
        int gi = tm * 10 + i;
        #pragma unroll
        for (int u = 0; u < 5; u++)
            *(float2*)&Sp[(size_t)gi * NN + tn * 10 + 2 * u] = unpk(acc[i][u]);
    }
}

// ---------------- K3c: reduce split-K + scale + softmax ---------------------
__global__ __launch_bounds__(256) void softmax2(const float* __restrict__ temp)
{
    const int warp = (blockIdx.x * 256 + threadIdx.x) >> 5;
    const int lane = threadIdx.x & 31;
    if (warp >= BH * NN) return;
    const int bh = warp / NN, i = warp % NN;
    const int h = bh & 3;
    const float scale_i = g_invq[bh * NN + i] * temp[h];
    float vals[5];
    float mx = -1e30f;
    #pragma unroll
    for (int j5 = 0; j5 < 5; j5++) {
        int j = lane + j5 * 32;
        float s = 0.f;
        #pragma unroll
        for (int ks = 0; ks < KSPL; ks++)
            s += g_Spart[(((size_t)ks * BH + bh) * NN + i) * NN + j];
        vals[j5] = s * scale_i * g_invk[bh * NN + j];
        mx = fmaxf(mx, vals[j5]);
    }
    #pragma unroll
    for (int off = 16; off; off >>= 1) mx = fmaxf(mx, __shfl_xor_sync(0xffffffffu, mx, off));
    float s = 0.f;
    #pragma unroll
    for (int j5 = 0; j5 < 5; j5++) { vals[j5] = __expf(vals[j5] - mx); s += vals[j5]; }
    #pragma unroll
    for (int off = 16; off; off >>= 1) s += __shfl_xor_sync(0xffffffffu, s, off);
    const float invs = 1.f / s;
    float* row = g_S + (size_t)bh * NN * NN + (size_t)i * NN;
    #pragma unroll
    for (int j5 = 0; j5 < 5; j5++) row[lane + j5 * 32] = vals[j5] * invs;
}

// ---------------- K3d: O = P V, FFMA2 ---------------------------------------
// tile 80(i) x 256(d), micro 5x(8x2), 256 threads, k chunked by 32.
// Dynamic smem: Psd[32][164] duplicated, Vs[32][260].
__global__ __launch_bounds__(256) void pv_gemm3()
{
    extern __shared__ __align__(16) float sm[];
    float (*Psd)[164] = (float(*)[164])sm;                    // [k][2*i], i<80
    float (*Vs)[260]  = (float(*)[260])(sm + 32 * 164);       // [k][d]
    const int bh = blockIdx.z;
    const int b = bh >> 2, h = bh & 3;
    const int i0 = blockIdx.y * 80;
    const int d0 = blockIdx.x * 256;
    const float* P = g_S + (size_t)bh * NN * NN;
    const float* V = g_qkv1 + ((size_t)b * C3 + 2 * CC + h * CPH) * THW;
    float*       O = g_O   + ((size_t)b * CC + h * CPH) * THW;
    const int tid = threadIdx.x;
    const int tm = tid >> 4, tn = tid & 15;

    unsigned long long acc[5][8];
    #pragma unroll
    for (int i = 0; i < 5; i++)
        #pragma unroll
        for (int j = 0; j < 8; j++) acc[i][j] = 0ull;

    for (int kb = 0; kb < NN; kb += 32) {
        // P tile 80 x 32 -> Psd[k][2i] duplicated
        #pragma unroll
        for (int j = 0; j < 3; j++) {
            int idx = tid + j * 256;
            if (idx < 640) {
                int row = idx >> 3;          // 0..79
                int col = (idx & 7) * 4;
                float4 v = *(const float4*)&P[(size_t)(i0 + row) * NN + kb + col];
                *(unsigned long long*)&Psd[col + 0][2 * row] = dup2(v.x);
                *(unsigned long long*)&Psd[col + 1][2 * row] = dup2(v.y);
                *(unsigned long long*)&Psd[col + 2][2 * row] = dup2(v.z);
                *(unsigned long long*)&Psd[col + 3][2 * row] = dup2(v.w);
            }
        }
        // V tile 32 x 256 -> Vs[k][d]
        #pragma unroll
        for (int j = 0; j < 8; j++) {
            int idx = tid + j * 256;         // 0..2047
            int row = idx >> 6;              // 0..31
            int col = (idx & 63) * 4;
            *(float4*)&Vs[row][col] = *(const float4*)&V[(size_t)(kb + row) * DD + d0 + col];
        }
        __syncthreads();
        #pragma unroll 4
        for (int k = 0; k < 32; k++) {
            unsigned long long a[5], bp[8];
            #pragma unroll
            for (int v = 0; v < 5; v++) a[v] = lds64(&Psd[k][10 * tm + 2 * v]);
            #pragma unroll
            for (int u = 0; u < 8; u++) bp[u] = lds64(&Vs[k][2 * tn + 32 * u]);
            #pragma unroll
            for (int v = 0; v < 5; v++)
                #pragma unroll
                for (int u = 0; u < 8; u++) ffma2(acc[v][u], a[v], bp[u]);
        }
        __syncthreads();
    }
    #pragma unroll
    for (int v = 0; v < 5; v++) {
        size_t base = (size_t)(i0 + tm * 5 + v) * DD + d0 + 2 * tn;
        #pragma unroll
        for (int u = 0; u < 8; u++)
            *(float2*)&O[base + 32 * u] = unpk(acc[v][u]);
    }
}

// ---------------- host launcher --------------------------------------------
extern "C" void kernel_launch(void* const* d_in, const int* in_sizes, int n_in,
                              void* d_out, int out_size)
{
    const float* x      = (const float*)d_in[0];
    const float* w_qkv  = (const float*)d_in[1];
    const float* w_dw   = (const float*)d_in[2];
    const float* w_t    = (const float*)d_in[3];
    const float* b_t    = (const float*)d_in[4];
    const float* temp   = (const float*)d_in[5];
    const float* w_out  = (const float*)d_in[6];
    float* out = (float*)d_out;

    float *qkv0, *obuf;
    cudaGetSymbolAddress((void**)&qkv0, g_qkv0);
    cudaGetSymbolAddress((void**)&obuf, g_O);

    const int qk_smem = (32 * 324 + 32 * 164) * 4;   // 62464 B
    const int pv_smem = (32 * 164 + 32 * 260) * 4;   // 54272 B
    cudaFuncSetAttribute(qk_gemm3, cudaFuncAttributeMaxDynamicSharedMemorySize, qk_smem);
    cudaFuncSetAttribute(pv_gemm3, cudaFuncAttributeMaxDynamicSharedMemorySize, pv_smem);

    // K1: qkv projection (192 x 40960 per batch)
    gemm_proj2<<<dim3(THW / 128, C3 / 64, BB), 128>>>(
        w_qkv, x, qkv0, (long)CC * THW, (long)C3 * THW);

    // K2: depthwise 3x3 + temporal mix
    dwconv_tmix<<<dim3(4, 4, BB * C3), 256>>>(w_dw, w_t, b_t);

    // K3a: q/k row norms
    norms_kernel<<<640, 256>>>();

    // K3b: split-K scores
    qk_gemm3<<<dim3(BH, KSPL), 256, qk_smem>>>();

    // K3c: reduce + scale + softmax
    softmax2<<<(BH * NN) / 8, 256>>>(temp);

    // K3d: O = P V
    pv_gemm3<<<dim3(DD / 256, NN / 80, BH), 256, pv_smem>>>();

    // K7: final projection -> d_out
    gemm_proj2<<<dim3(THW / 128, 1, BB), 128>>>(
        w_out, obuf, out, (long)CC * THW, (long)CC * THW);
}

// round 5
// speedup vs baseline: 1.9866x; 1.0520x over previous
#include <cuda_runtime.h>
#include <math.h>

#define BB 4
#define CC 64
#define C3 192
#define TT 10
#define HH 64
#define WW 64
#define HW 4096
#define THW 40960
#define HEADS 4
#define CPH 16
#define NN 160
#define DD 4096
#define BH (BB*HEADS)
#define KSPL 16
#define KCH (DD/KSPL)   // 256

// ---------------- scratch (device globals) ---------------------------------
__device__ float g_qkv0[(size_t)BB * C3 * THW];
__device__ float g_qkv1[(size_t)BB * C3 * THW];
__device__ float g_Spart[(size_t)KSPL * BH * NN * NN];
__device__ float g_S[(size_t)BH * NN * NN];
__device__ float g_invq[BH * NN];
__device__ float g_invk[BH * NN];
__device__ float g_O[(size_t)BB * CC * THW];

// ---------------- packed f32x2 helpers --------------------------------------
__device__ __forceinline__ void ffma2(unsigned long long& d,
                                      unsigned long long a, unsigned long long b) {
    asm("fma.rn.f32x2 %0, %1, %2, %0;" : "+l"(d) : "l"(a), "l"(b));
}
__device__ __forceinline__ unsigned long long dup2(float x) {
    unsigned long long r;
    asm("mov.b64 %0, {%1, %1};" : "=l"(r) : "f"(x));
    return r;
}
__device__ __forceinline__ float2 unpk(unsigned long long v) {
    float2 r;
    asm("mov.b64 {%0, %1}, %2;" : "=f"(r.x), "=f"(r.y) : "l"(v));
    return r;
}
__device__ __forceinline__ unsigned long long lds64(const float* p) {
    return *(const unsigned long long*)p;
}

// ---------------- K1 / K7: projection GEMM (FFMA2, 6 CTAs/SM) ---------------
__global__ __launch_bounds__(128) void gemm_proj2(
    const float* __restrict__ W, const float* __restrict__ X, float* __restrict__ Y,
    long xbstride, long ybstride)
{
    __shared__ __align__(16) float As2[32][132];
    __shared__ __align__(16) float Bs[32][132];
    const int b  = blockIdx.z;
    const int m0 = blockIdx.y * 64;
    const int p0 = blockIdx.x * 128;
    const float* Xb = X + (size_t)b * xbstride;
    float*       Yb = Y + (size_t)b * ybstride;
    const int tid = threadIdx.x;
    const int tm = tid >> 4, tn = tid & 15;

    unsigned long long acc[8][4];
    #pragma unroll
    for (int i = 0; i < 8; i++)
        #pragma unroll
        for (int j = 0; j < 4; j++) acc[i][j] = 0ull;

    for (int kb = 0; kb < 64; kb += 32) {
        #pragma unroll
        for (int j = 0; j < 4; j++) {
            int idx = tid + j * 128;
            int row = idx >> 3;
            int kc  = (idx & 7) * 4;
            float4 w4 = *(const float4*)&W[(size_t)(m0 + row) * 64 + kb + kc];
            *(unsigned long long*)&As2[kc + 0][2 * row] = dup2(w4.x);
            *(unsigned long long*)&As2[kc + 1][2 * row] = dup2(w4.y);
            *(unsigned long long*)&As2[kc + 2][2 * row] = dup2(w4.z);
            *(unsigned long long*)&As2[kc + 3][2 * row] = dup2(w4.w);
        }
        #pragma unroll
        for (int j = 0; j < 8; j++) {
            int idx = tid + j * 128;
            int row = idx >> 5;
            int col = (idx & 31) * 4;
            *(float4*)&Bs[row][col] = *(const float4*)&Xb[(size_t)(kb + row) * THW + p0 + col];
        }
        __syncthreads();
        #pragma unroll 4
        for (int k = 0; k < 32; k++) {
            unsigned long long a[8], bp[4];
            #pragma unroll
            for (int mi = 0; mi < 8; mi++) a[mi] = lds64(&As2[k][2 * (tm * 8 + mi)]);
            #pragma unroll
            for (int u = 0; u < 4; u++)    bp[u] = lds64(&Bs[k][2 * tn + 32 * u]);
            #pragma unroll
            for (int mi = 0; mi < 8; mi++)
                #pragma unroll
                for (int u = 0; u < 4; u++) ffma2(acc[mi][u], a[mi], bp[u]);
        }
        __syncthreads();
    }
    #pragma unroll
    for (int mi = 0; mi < 8; mi++) {
        size_t base = (size_t)(m0 + tm * 8 + mi) * THW + p0 + 2 * tn;
        #pragma unroll
        for (int u = 0; u < 4; u++)
            *(float2*)&Yb[base + 32 * u] = unpk(acc[mi][u]);
    }
}

// ---------------- K2: depthwise 3x3 + temporal mix (fused) ------------------
__global__ __launch_bounds__(256) void dwconv_tmix(
    const float* __restrict__ wdw, const float* __restrict__ wt,
    const float* __restrict__ bt)
{
    __shared__ float tile[TT][18][18];
    const int bc = blockIdx.z;
    const int c  = bc % C3;
    const int h0 = blockIdx.y * 16, w0 = blockIdx.x * 16;
    const float* src = g_qkv0 + (size_t)bc * THW;
    float*       dst = g_qkv1 + (size_t)bc * THW;
    const int tid = threadIdx.x;

    for (int idx = tid; idx < TT * 18 * 18; idx += 256) {
        int t = idx / 324, rem = idx % 324;
        int y = rem / 18, x = rem % 18;
        int gh = h0 + y - 1, gw = w0 + x - 1;
        float v = 0.f;
        if (gh >= 0 && gh < HH && gw >= 0 && gw < WW)
            v = src[(size_t)t * HW + gh * WW + gw];
        tile[t][y][x] = v;
    }
    __syncthreads();

    float wd[9];
    #pragma unroll
    for (int i = 0; i < 9; i++) wd[i] = wdw[c * 9 + i];

    const int y = tid >> 4, x = tid & 15;
    float cv[TT];
    #pragma unroll
    for (int t = 0; t < TT; t++) {
        float s = 0.f;
        #pragma unroll
        for (int kh = 0; kh < 3; kh++)
            #pragma unroll
            for (int kw = 0; kw < 3; kw++)
                s += wd[kh * 3 + kw] * tile[t][y + kh][x + kw];
        cv[t] = s;
    }
    const int hw = (h0 + y) * WW + (w0 + x);
    #pragma unroll
    for (int s = 0; s < TT; s++) {
        float o = bt[s];
        #pragma unroll
        for (int t = 0; t < TT; t++) o += wt[s * TT + t] * cv[t];
        dst[(size_t)s * HW + hw] = o;
    }
}

// ---------------- K3a: L2 norms of q/k rows ---------------------------------
__global__ __launch_bounds__(256) void norms_kernel()
{
    const int warp = (blockIdx.x * 256 + threadIdx.x) >> 5;
    const int lane = threadIdx.x & 31;
    if (warp >= 2 * BH * NN) return;
    const int qk = warp / (BH * NN);
    const int r  = warp % (BH * NN);
    const int bh = r / NN, i = r % NN;
    const int b = bh / HEADS, h = bh % HEADS;
    const float* row = g_qkv1 + ((size_t)b * C3 + qk * CC + h * CPH) * THW + (size_t)i * DD;
    float s = 0.f;
    for (int d = lane * 4; d < DD; d += 128) {
        float4 v = *(const float4*)&row[d];
        s += v.x * v.x + v.y * v.y + v.z * v.z + v.w * v.w;
    }
    #pragma unroll
    for (int off = 16; off; off >>= 1) s += __shfl_xor_sync(0xffffffffu, s, off);
    if (lane == 0) {
        float inv = 1.f / fmaxf(sqrtf(s), 1e-12f);
        (qk ? g_invk : g_invq)[bh * NN + i] = inv;
    }
}

// ---------------- K3b: S partials = Q K^T, split-K, FFMA2, double-buffered --
// Stage layout (floats): Qs2 32x324 (dup) then Ks 32x164. Two stages.
#define QK_STG (32 * 324 + 32 * 164)

__global__ __launch_bounds__(256) void qk_gemm4()
{
    extern __shared__ __align__(16) float sm[];
    const int bh = blockIdx.x;
    const int ks = blockIdx.y;
    const int b = bh >> 2, h = bh & 3;
    const float* Q  = g_qkv1 + ((size_t)b * C3 + h * CPH) * THW;
    const float* Kp = Q + (size_t)CC * THW;
    const int tid = threadIdx.x;
    const int tm = tid >> 4, tn = tid & 15;

    // per-thread load coordinates (5 segments)
    int lrow[5], lkc[5];
    #pragma unroll
    for (int j = 0; j < 5; j++) {
        int idx = tid + j * 256;
        lrow[j] = idx >> 3;
        lkc[j]  = (idx & 7) * 4;
    }

    unsigned long long acc[10][5];
    #pragma unroll
    for (int i = 0; i < 10; i++)
        #pragma unroll
        for (int j = 0; j < 5; j++) acc[i][j] = 0ull;

    float4 qr[5], kr[5];
    const int kb0 = ks * KCH;

    // prologue: load + store chunk 0
    #pragma unroll
    for (int j = 0; j < 5; j++) {
        qr[j] = *(const float4*)&Q [(size_t)lrow[j] * DD + kb0 + lkc[j]];
        kr[j] = *(const float4*)&Kp[(size_t)lrow[j] * DD + kb0 + lkc[j]];
    }
    {
        float* Qs2 = sm;
        float* Ks  = sm + 32 * 324;
        #pragma unroll
        for (int j = 0; j < 5; j++) {
            *(unsigned long long*)&Qs2[(lkc[j] + 0) * 324 + 2 * lrow[j]] = dup2(qr[j].x);
            *(unsigned long long*)&Qs2[(lkc[j] + 1) * 324 + 2 * lrow[j]] = dup2(qr[j].y);
            *(unsigned long long*)&Qs2[(lkc[j] + 2) * 324 + 2 * lrow[j]] = dup2(qr[j].z);
            *(unsigned long long*)&Qs2[(lkc[j] + 3) * 324 + 2 * lrow[j]] = dup2(qr[j].w);
            Ks[(lkc[j] + 0) * 164 + lrow[j]] = kr[j].x;
            Ks[(lkc[j] + 1) * 164 + lrow[j]] = kr[j].y;
            Ks[(lkc[j] + 2) * 164 + lrow[j]] = kr[j].z;
            Ks[(lkc[j] + 3) * 164 + lrow[j]] = kr[j].w;
        }
    }
    __syncthreads();

    for (int c = 0; c < 8; c++) {
        // prefetch next chunk into registers (latency hidden under compute)
        if (c < 7) {
            const int kb = kb0 + (c + 1) * 32;
            #pragma unroll
            for (int j = 0; j < 5; j++) {
                qr[j] = *(const float4*)&Q [(size_t)lrow[j] * DD + kb + lkc[j]];
                kr[j] = *(const float4*)&Kp[(size_t)lrow[j] * DD + kb + lkc[j]];
            }
        }
        const float* Qs2 = sm + (c & 1) * QK_STG;
        const float* Ks  = Qs2 + 32 * 324;
        #pragma unroll 4
        for (int k = 0; k < 32; k++) {
            unsigned long long a[10], bp[5];
            #pragma unroll
            for (int i = 0; i < 10; i++) a[i] = lds64(&Qs2[k * 324 + 20 * tm + 2 * i]);
            #pragma unroll
            for (int u = 0; u < 5; u++) bp[u] = lds64(&Ks[k * 164 + 10 * tn + 2 * u]);
            #pragma unroll
            for (int i = 0; i < 10; i++)
                #pragma unroll
                for (int u = 0; u < 5; u++) ffma2(acc[i][u], a[i], bp[u]);
        }
        if (c < 7) {
            float* Qw = sm + ((c + 1) & 1) * QK_STG;
            float* Kw = Qw + 32 * 324;
            #pragma unroll
            for (int j = 0; j < 5; j++) {
                *(unsigned long long*)&Qw[(lkc[j] + 0) * 324 + 2 * lrow[j]] = dup2(qr[j].x);
                *(unsigned long long*)&Qw[(lkc[j] + 1) * 324 + 2 * lrow[j]] = dup2(qr[j].y);
                *(unsigned long long*)&Qw[(lkc[j] + 2) * 324 + 2 * lrow[j]] = dup2(qr[j].z);
                *(unsigned long long*)&Qw[(lkc[j] + 3) * 324 + 2 * lrow[j]] = dup2(qr[j].w);
                Kw[(lkc[j] + 0) * 164 + lrow[j]] = kr[j].x;
                Kw[(lkc[j] + 1) * 164 + lrow[j]] = kr[j].y;
                Kw[(lkc[j] + 2) * 164 + lrow[j]] = kr[j].z;
                Kw[(lkc[j] + 3) * 164 + lrow[j]] = kr[j].w;
            }
        }
        __syncthreads();
    }

    float* Sp = g_Spart + ((size_t)ks * BH + bh) * NN * NN;
    #pragma unroll
    for (int i = 0; i < 10; i++) {
        int gi = tm * 10 + i;
        #pragma unroll
        for (int u = 0; u < 5; u++)
            *(float2*)&Sp[(size_t)gi * NN + tn * 10 + 2 * u] = unpk(acc[i][u]);
    }
}

// ---------------- K3c: reduce split-K + scale + softmax ---------------------
__global__ __launch_bounds__(256) void softmax2(const float* __restrict__ temp)
{
    const int warp = (blockIdx.x * 256 + threadIdx.x) >> 5;
    const int lane = threadIdx.x & 31;
    if (warp >= BH * NN) return;
    const int bh = warp / NN, i = warp % NN;
    const int h = bh & 3;
    const float scale_i = g_invq[bh * NN + i] * temp[h];
    float vals[5];
    float mx = -1e30f;
    #pragma unroll
    for (int j5 = 0; j5 < 5; j5++) {
        int j = lane + j5 * 32;
        float s = 0.f;
        #pragma unroll
        for (int ks = 0; ks < KSPL; ks++)
            s += g_Spart[(((size_t)ks * BH + bh) * NN + i) * NN + j];
        vals[j5] = s * scale_i * g_invk[bh * NN + j];
        mx = fmaxf(mx, vals[j5]);
    }
    #pragma unroll
    for (int off = 16; off; off >>= 1) mx = fmaxf(mx, __shfl_xor_sync(0xffffffffu, mx, off));
    float s = 0.f;
    #pragma unroll
    for (int j5 = 0; j5 < 5; j5++) { vals[j5] = __expf(vals[j5] - mx); s += vals[j5]; }
    #pragma unroll
    for (int off = 16; off; off >>= 1) s += __shfl_xor_sync(0xffffffffu, s, off);
    const float invs = 1.f / s;
    float* row = g_S + (size_t)bh * NN * NN + (size_t)i * NN;
    #pragma unroll
    for (int j5 = 0; j5 < 5; j5++) row[lane + j5 * 32] = vals[j5] * invs;
}

// ---------------- K3d: O = P V, FFMA2, double-buffered -----------------------
// Stage layout (floats): Psd 32x164 (dup) then Vs 32x260. Two stages.
#define PV_STG (32 * 164 + 32 * 260)

__global__ __launch_bounds__(256) void pv_gemm4()
{
    extern __shared__ __align__(16) float sm[];
    const int bh = blockIdx.z;
    const int b = bh >> 2, h = bh & 3;
    const int i0 = blockIdx.y * 80;
    const int d0 = blockIdx.x * 256;
    const float* P = g_S + (size_t)bh * NN * NN;
    const float* V = g_qkv1 + ((size_t)b * C3 + 2 * CC + h * CPH) * THW;
    float*       O = g_O   + ((size_t)b * CC + h * CPH) * THW;
    const int tid = threadIdx.x;
    const int tm = tid >> 4, tn = tid & 15;

    // P-load coords: idx = tid + j*256, valid idx<640 (j<3, partial j=2)
    // V-load coords: idx = tid + j*256, j<8
    unsigned long long acc[5][8];
    #pragma unroll
    for (int i = 0; i < 5; i++)
        #pragma unroll
        for (int j = 0; j < 8; j++) acc[i][j] = 0ull;

    float4 pr[3], vr[8];

    // prologue chunk 0
    #pragma unroll
    for (int j = 0; j < 3; j++) {
        int idx = tid + j * 256;
        if (idx < 640)
            pr[j] = *(const float4*)&P[(size_t)(i0 + (idx >> 3)) * NN + 0 + (idx & 7) * 4];
    }
    #pragma unroll
    for (int j = 0; j < 8; j++) {
        int idx = tid + j * 256;
        vr[j] = *(const float4*)&V[(size_t)(0 + (idx >> 6)) * DD + d0 + (idx & 63) * 4];
    }
    {
        float* Psd = sm;
        float* Vs  = sm + 32 * 164;
        #pragma unroll
        for (int j = 0; j < 3; j++) {
            int idx = tid + j * 256;
            if (idx < 640) {
                int row = idx >> 3, col = (idx & 7) * 4;
                *(unsigned long long*)&Psd[(col + 0) * 164 + 2 * row] = dup2(pr[j].x);
                *(unsigned long long*)&Psd[(col + 1) * 164 + 2 * row] = dup2(pr[j].y);
                *(unsigned long long*)&Psd[(col + 2) * 164 + 2 * row] = dup2(pr[j].z);
                *(unsigned long long*)&Psd[(col + 3) * 164 + 2 * row] = dup2(pr[j].w);
            }
        }
        #pragma unroll
        for (int j = 0; j < 8; j++) {
            int idx = tid + j * 256;
            *(float4*)&Vs[(idx >> 6) * 260 + (idx & 63) * 4] = vr[j];
        }
    }
    __syncthreads();

    for (int c = 0; c < 5; c++) {
        if (c < 4) {
            const int kb = (c + 1) * 32;
            #pragma unroll
            for (int j = 0; j < 3; j++) {
                int idx = tid + j * 256;
                if (idx < 640)
                    pr[j] = *(const float4*)&P[(size_t)(i0 + (idx >> 3)) * NN + kb + (idx & 7) * 4];
            }
            #pragma unroll
            for (int j = 0; j < 8; j++) {
                int idx = tid + j * 256;
                vr[j] = *(const float4*)&V[(size_t)(kb + (idx >> 6)) * DD + d0 + (idx & 63) * 4];
            }
        }
        const float* Psd = sm + (c & 1) * PV_STG;
        const float* Vs  = Psd + 32 * 164;
        #pragma unroll 4
        for (int k = 0; k < 32; k++) {
            unsigned long long a[5], bp[8];
            #pragma unroll
            for (int v = 0; v < 5; v++) a[v] = lds64(&Psd[k * 164 + 10 * tm + 2 * v]);
            #pragma unroll
            for (int u = 0; u < 8; u++) bp[u] = lds64(&Vs[k * 260 + 2 * tn + 32 * u]);
            #pragma unroll
            for (int v = 0; v < 5; v++)
                #pragma unroll
                for (int u = 0; u < 8; u++) ffma2(acc[v][u], a[v], bp[u]);
        }
        if (c < 4) {
            float* Pw = sm + ((c + 1) & 1) * PV_STG;
            float* Vw = Pw + 32 * 164;
            #pragma unroll
            for (int j = 0; j < 3; j++) {
                int idx = tid + j * 256;
                if (idx < 640) {
                    int row = idx >> 3, col = (idx & 7) * 4;
                    *(unsigned long long*)&Pw[(col + 0) * 164 + 2 * row] = dup2(pr[j].x);
                    *(unsigned long long*)&Pw[(col + 1) * 164 + 2 * row] = dup2(pr[j].y);
                    *(unsigned long long*)&Pw[(col + 2) * 164 + 2 * row] = dup2(pr[j].z);
                    *(unsigned long long*)&Pw[(col + 3) * 164 + 2 * row] = dup2(pr[j].w);
                }
            }
            #pragma unroll
            for (int j = 0; j < 8; j++) {
                int idx = tid + j * 256;
                *(float4*)&Vw[(idx >> 6) * 260 + (idx & 63) * 4] = vr[j];
            }
        }
        __syncthreads();
    }

    #pragma unroll
    for (int v = 0; v < 5; v++) {
        size_t base = (size_t)(i0 + tm * 5 + v) * DD + d0 + 2 * tn;
        #pragma unroll
        for (int u = 0; u < 8; u++)
            *(float2*)&O[base + 32 * u] = unpk(acc[v][u]);
    }
}

// ---------------- host launcher --------------------------------------------
extern "C" void kernel_launch(void* const* d_in, const int* in_sizes, int n_in,
                              void* d_out, int out_size)
{
    const float* x      = (const float*)d_in[0];
    const float* w_qkv  = (const float*)d_in[1];
    const float* w_dw   = (const float*)d_in[2];
    const float* w_t    = (const float*)d_in[3];
    const float* b_t    = (const float*)d_in[4];
    const float* temp   = (const float*)d_in[5];
    const float* w_out  = (const float*)d_in[6];
    float* out = (float*)d_out;

    float *qkv0, *obuf;
    cudaGetSymbolAddress((void**)&qkv0, g_qkv0);
    cudaGetSymbolAddress((void**)&obuf, g_O);

    const int qk_smem = 2 * QK_STG * 4;   // 124928 B
    const int pv_smem = 2 * PV_STG * 4;   // 108544 B
    cudaFuncSetAttribute(qk_gemm4, cudaFuncAttributeMaxDynamicSharedMemorySize, qk_smem);
    cudaFuncSetAttribute(pv_gemm4, cudaFuncAttributeMaxDynamicSharedMemorySize, pv_smem);

    // K1: qkv projection (192 x 40960 per batch)
    gemm_proj2<<<dim3(THW / 128, C3 / 64, BB), 128>>>(
        w_qkv, x, qkv0, (long)CC * THW, (long)C3 * THW);

    // K2: depthwise 3x3 + temporal mix
    dwconv_tmix<<<dim3(4, 4, BB * C3), 256>>>(w_dw, w_t, b_t);

    // K3a: q/k row norms
    norms_kernel<<<640, 256>>>();

    // K3b: split-K scores (double-buffered)
    qk_gemm4<<<dim3(BH, KSPL), 256, qk_smem>>>();

    // K3c: reduce + scale + softmax
    softmax2<<<(BH * NN) / 8, 256>>>(temp);

    // K3d: O = P V (double-buffered)
    pv_gemm4<<<dim3(DD / 256, NN / 80, BH), 256, pv_smem>>>();

    // K7: final projection -> d_out
    gemm_proj2<<<dim3(THW / 128, 1, BB), 128>>>(
        w_out, obuf, out, (long)CC * THW, (long)CC * THW);
}